// round 7
// baseline (speedup 1.0000x reference)
#include <cuda_runtime.h>
#include <cuda_bf16.h>
#include <cstdint>

// SpatialTransformer: 3D trilinear grid-sample, border padding, align_corners=True.
// img [2,1,160,192,224], flow [2,3,160,192,224], out [2,1,160,192,224].
//
// px = (x+flow0+1)*111.5 clamps to 223 for ~98% of voxels (fx=0) -> bilinear on
// the x=223 border slice, precomputed CORNER-PACKED (bs4): one LDG.128 + 6 flops.
// R7: flow is streamed via cp.async.bulk (TMA 1D) into a 3-stage smem ring with
// mbarriers; ~888 semi-persistent CTAs each process ~15 tiles of 1024 voxels.
// This takes the 577-cycle flow DRAM latency off the warp scoreboard.

#define DD 160
#define HH 192
#define WW 224
#define HW (HH * WW)
#define NVOX (DD * HH * WW)     // 6,881,280
#define NB 2
#define NSLICE (NB * DD * HH)   // 61,440

#define TILE 1024               // voxels per tile (4KB per flow channel)
#define RS 3                    // pipeline stages
#define NTILES ((NB * NVOX) / TILE)      // 13,440 (exact)
#define TILES_PER_B (NVOX / TILE)        // 6,720 (exact)
#define TPB 256
#define GRID_MAIN (148 * 6)     // 888 CTAs, 6/SM (smem-limited)
#define STAGE_BYTES (3 * TILE * 4)       // 12,288

__device__ float4 g_bs4[NSLICE];   // corner-packed border slice

__global__ __launch_bounds__(256) void build_bs4_kernel(
    const float* __restrict__ img)
{
    int idx = blockIdx.x * blockDim.x + threadIdx.x;
    if (idx >= NSLICE) return;
    int b = idx / (DD * HH);
    int r = idx - b * (DD * HH);      // z*HH + y
    int z = r / HH;
    int y = r - z * HH;
    int y1 = min(y + 1, HH - 1);
    int z1 = min(z + 1, DD - 1);

    const float* im = img + (size_t)b * NVOX + (WW - 1);
    float4 v;
    v.x = __ldg(im + (size_t)z  * HW + y  * WW);
    v.y = __ldg(im + (size_t)z  * HW + y1 * WW);
    v.z = __ldg(im + (size_t)z1 * HW + y  * WW);
    v.w = __ldg(im + (size_t)z1 * HW + y1 * WW);
    g_bs4[idx] = v;
}

// ---------- mbarrier / bulk-copy helpers ----------
__device__ __forceinline__ uint32_t smem_u32(const void* p) {
    uint32_t a;
    asm("{ .reg .u64 t; cvta.to.shared.u64 t, %1; cvt.u32.u64 %0, t; }"
        : "=r"(a) : "l"(p));
    return a;
}
__device__ __forceinline__ void mbar_init(uint32_t addr, uint32_t count) {
    asm volatile("mbarrier.init.shared.b64 [%0], %1;" :: "r"(addr), "r"(count) : "memory");
}
__device__ __forceinline__ void mbar_expect_tx(uint32_t addr, uint32_t bytes) {
    asm volatile("mbarrier.arrive.expect_tx.shared.b64 _, [%0], %1;"
                 :: "r"(addr), "r"(bytes) : "memory");
}
__device__ __forceinline__ void mbar_arrive(uint32_t addr) {
    asm volatile("mbarrier.arrive.shared.b64 _, [%0];" :: "r"(addr) : "memory");
}
__device__ __forceinline__ void mbar_wait(uint32_t addr, uint32_t parity) {
    asm volatile(
        "{\n\t.reg .pred P;\n\t"
        "WL_%=:\n\t"
        "mbarrier.try_wait.parity.acquire.cta.shared::cta.b64 P, [%0], %1, 0x989680;\n\t"
        "@!P bra WL_%=;\n\t}"
        :: "r"(addr), "r"(parity) : "memory");
}
__device__ __forceinline__ void bulk_copy_4k(uint32_t smem_dst, const void* gmem_src,
                                             uint32_t mbar) {
    asm volatile(
        "cp.async.bulk.shared::cta.global.mbarrier::complete_tx::bytes [%0], [%1], %2, [%3];"
        :: "r"(smem_dst), "l"(gmem_src), "r"((uint32_t)(TILE * 4)), "r"(mbar)
        : "memory");
}

__global__ __launch_bounds__(TPB) void st3d_kernel(
    const float* __restrict__ img,
    const float* __restrict__ flow,
    float* __restrict__ out)
{
    __shared__ __align__(16) float sm_flow[RS][3][TILE];   // 36 KB
    __shared__ __align__(16) uint64_t sm_mbar[2 * RS];     // full[s]=2s, empty[s]=2s+1

    const int tid = threadIdx.x;
    const int cta = blockIdx.x;

    const uint32_t mb = smem_u32(sm_mbar);
    #define FULL_BAR(s)  (mb + (uint32_t)(s) * 16u)
    #define EMPTY_BAR(s) (mb + (uint32_t)(s) * 16u + 8u)

    if (tid == 0) {
        #pragma unroll
        for (int s = 0; s < RS; ++s) {
            mbar_init(FULL_BAR(s), 1);
            mbar_init(EMPTY_BAR(s), TPB);
        }
    }
    __syncthreads();

    // tiles handled by this CTA: t = cta + j*GRID_MAIN, j = 0..NT-1
    const int NT = (NTILES - cta + GRID_MAIN - 1) / GRID_MAIN;

    // producer prologue: buffers known-empty, fill up to RS stages
    if (tid == 0) {
        const int np = (NT < RS) ? NT : RS;
        for (int p = 0; p < np; ++p) {
            const int t = cta + p * GRID_MAIN;
            const int b = (t >= TILES_PER_B) ? 1 : 0;
            const int i0 = (t - b * TILES_PER_B) * TILE;
            const float* fb = flow + (size_t)b * 3 * NVOX + i0;
            mbar_expect_tx(FULL_BAR(p), STAGE_BYTES);
            bulk_copy_4k(smem_u32(&sm_flow[p][0][0]), fb,            FULL_BAR(p));
            bulk_copy_4k(smem_u32(&sm_flow[p][1][0]), fb + NVOX,     FULL_BAR(p));
            bulk_copy_4k(smem_u32(&sm_flow[p][2][0]), fb + 2 * NVOX, FULL_BAR(p));
        }
    }

    for (int j = 0; j < NT; ++j) {
        const int s = j % RS;
        const uint32_t parity = (uint32_t)((j / RS) & 1);

        mbar_wait(FULL_BAR(s), parity);

        const int t = cta + j * GRID_MAIN;
        const int g0 = t * TILE + tid * 4;          // 4 consecutive voxels
        const int b = (g0 >= NVOX) ? 1 : 0;
        const int i = g0 - b * NVOX;

        const int z = i / HW;
        const int rem = i - z * HW;
        const int y = rem / WW;
        const int x = rem - y * WW;

        const float4 f0 = *reinterpret_cast<const float4*>(&sm_flow[s][0][tid * 4]);
        const float4 f1 = *reinterpret_cast<const float4*>(&sm_flow[s][1][tid * 4]);
        const float4 f2 = *reinterpret_cast<const float4*>(&sm_flow[s][2][tid * 4]);

        const float f0a[4] = {f0.x, f0.y, f0.z, f0.w};
        const float f1a[4] = {f1.x, f1.y, f1.z, f1.w};
        const float f2a[4] = {f2.x, f2.y, f2.z, f2.w};

        const float* im = img + (size_t)b * NVOX;
        const float4* bs4 = g_bs4 + b * (DD * HH);

        float oa[4];
        #pragma unroll
        for (int k = 0; k < 4; ++k) {
            // raw px; *0.5f*223.0f == *111.5f bitwise (0.5*223 exact)
            const float pxr = ((float)(x + k) + f0a[k] + 1.0f) * 111.5f;

            float py = (float)y + f1a[k];
            float pz = (float)z + f2a[k];
            py = fminf(fmaxf(py, 0.0f), (float)(HH - 1));
            pz = fminf(fmaxf(pz, 0.0f), (float)(DD - 1));

            const float y0f = floorf(py);
            const float z0f = floorf(pz);
            const float fy = py - y0f;
            const float fz = pz - z0f;
            const int y0 = (int)y0f;
            const int z0 = (int)z0f;

            float res;
            if (pxr >= (float)(WW - 1)) {
                // border fast path: fx == 0; all 4 corners in one packed LDG.128
                const float4 v = __ldg(bs4 + z0 * HH + y0);
                const float c0 = v.x + (v.y - v.x) * fy;
                const float c1 = v.z + (v.w - v.z) * fy;
                res = c0 + (c1 - c0) * fz;
            } else {
                const float px = fmaxf(pxr, 0.0f);      // px < 223 here
                const float x0f = floorf(px);
                const float fx = px - x0f;
                const int x0 = (int)x0f;
                const int x1 = min(x0 + 1, WW - 1);
                const int y1 = min(y0 + 1, HH - 1);
                const int z1 = min(z0 + 1, DD - 1);

                const long long zb0 = (long long)z0 * HW;
                const long long zb1 = (long long)z1 * HW;
                const int yb0 = y0 * WW;
                const int yb1 = y1 * WW;

                const float c000 = __ldg(im + zb0 + yb0 + x0);
                const float c001 = __ldg(im + zb0 + yb0 + x1);
                const float c010 = __ldg(im + zb0 + yb1 + x0);
                const float c011 = __ldg(im + zb0 + yb1 + x1);
                const float c100 = __ldg(im + zb1 + yb0 + x0);
                const float c101 = __ldg(im + zb1 + yb0 + x1);
                const float c110 = __ldg(im + zb1 + yb1 + x0);
                const float c111 = __ldg(im + zb1 + yb1 + x1);

                const float c00 = c000 + (c001 - c000) * fx;
                const float c01 = c010 + (c011 - c010) * fx;
                const float c10 = c100 + (c101 - c100) * fx;
                const float c11 = c110 + (c111 - c110) * fx;
                const float c0 = c00 + (c01 - c00) * fy;
                const float c1 = c10 + (c11 - c10) * fy;
                res = c0 + (c1 - c0) * fz;
            }
            oa[k] = res;
        }

        __stcs(reinterpret_cast<float4*>(out + g0),
               make_float4(oa[0], oa[1], oa[2], oa[3]));

        // done reading stage s
        mbar_arrive(EMPTY_BAR(s));

        // producer refills stage s for tile j+RS once all consumers are done
        if (tid == 0) {
            const int jn = j + RS;
            if (jn < NT) {
                mbar_wait(EMPTY_BAR(s), parity);
                const int tn = cta + jn * GRID_MAIN;
                const int bn = (tn >= TILES_PER_B) ? 1 : 0;
                const int i0n = (tn - bn * TILES_PER_B) * TILE;
                const float* fbn = flow + (size_t)bn * 3 * NVOX + i0n;
                mbar_expect_tx(FULL_BAR(s), STAGE_BYTES);
                bulk_copy_4k(smem_u32(&sm_flow[s][0][0]), fbn,            FULL_BAR(s));
                bulk_copy_4k(smem_u32(&sm_flow[s][1][0]), fbn + NVOX,     FULL_BAR(s));
                bulk_copy_4k(smem_u32(&sm_flow[s][2][0]), fbn + 2 * NVOX, FULL_BAR(s));
            }
        }
    }
}

extern "C" void kernel_launch(void* const* d_in, const int* in_sizes, int n_in,
                              void* d_out, int out_size)
{
    const float* img  = (const float*)d_in[0];
    const float* flow = (const float*)d_in[1];
    float* out = (float*)d_out;

    build_bs4_kernel<<<(NSLICE + 255) / 256, 256>>>(img);
    st3d_kernel<<<GRID_MAIN, TPB>>>(img, flow, out);
}

// round 8
// speedup vs baseline: 1.9859x; 1.9859x over previous
#include <cuda_runtime.h>
#include <cuda_bf16.h>

// SpatialTransformer: 3D trilinear grid-sample, border padding, align_corners=True.
// img [2,1,160,192,224], flow [2,3,160,192,224], out [2,1,160,192,224].
//
// px = (x+flow0+1)*111.5 clamps to 223 for ~98% of voxels (fx=0) -> bilinear on
// the x=223 border slice. R8: the WHOLE per-batch slice (160x192 floats, 123 KB)
// lives in shared memory (row-padded to 193 for bank spread), so the fast path
// is 4 LDS + 6 FFMA -- no L2 round trip, no gather traffic. 148 CTAs x 1024 thr,
// one CTA per SM, batch split 74/74. Flow: float4 __ldcs + 1-iter prefetch.

#define DD 160
#define HH 192
#define WW 224
#define HW (HH * WW)
#define NVOX (DD * HH * WW)     // 6,881,280
#define NB 2
#define NSLICE (NB * DD * HH)   // 61,440

#define SP 193                  // padded smem row stride (bank spread)
#define SLICE_FLOATS (DD * SP)  // 30,880
#define SLICE_BYTES (SLICE_FLOATS * 4)  // 123,520

#define CTAS_PER_B 74
#define GRID_MAIN (2 * CTAS_PER_B)      // 148
#define TPB 1024
#define GROUPS (NVOX / 4)               // 1,720,320 float4-groups per batch
#define GSTRIDE (CTAS_PER_B * TPB)      // 75,776

__device__ float g_bslice[NSLICE];      // compact [b][z*HH+y] = img[b][z][y][223]

__global__ __launch_bounds__(256) void extract_border_kernel(
    const float* __restrict__ img)
{
    int idx = blockIdx.x * blockDim.x + threadIdx.x;
    if (idx >= NSLICE) return;
    int b = idx / (DD * HH);
    int r = idx - b * (DD * HH);      // z*HH + y
    int z = r / HH;
    int y = r - z * HH;
    g_bslice[idx] = img[(size_t)b * NVOX + (size_t)z * HW + y * WW + (WW - 1)];
}

__global__ __launch_bounds__(TPB, 1) void st3d_kernel(
    const float* __restrict__ img,
    const float* __restrict__ flow,
    float* __restrict__ out)
{
    extern __shared__ float s_slice[];   // [DD][SP]

    const int tid = threadIdx.x;
    const int cta = blockIdx.x;
    const int b = (cta >= CTAS_PER_B) ? 1 : 0;
    const int c = cta - b * CTAS_PER_B;

    // ---- fill smem slice (row-padded) from compact global slice ----
    {
        const float* src = g_bslice + b * (DD * HH);
        for (int idx = tid; idx < DD * HH; idx += TPB) {
            const int z = idx / HH;
            const int y = idx - z * HH;
            s_slice[z * SP + y] = __ldg(src + idx);
        }
    }
    __syncthreads();

    const float* fb = flow + (size_t)b * 3 * NVOX;
    const float* im = img + (size_t)b * NVOX;
    float* ob = out + (size_t)b * NVOX;

    // ---- main loop with 1-iteration flow prefetch ----
    int g = c * TPB + tid;               // group id (4 voxels) within batch
    bool valid = (g < GROUPS);
    float4 nf0, nf1, nf2;
    if (valid) {
        const int i = g * 4;
        nf0 = __ldcs(reinterpret_cast<const float4*>(fb + i));
        nf1 = __ldcs(reinterpret_cast<const float4*>(fb + NVOX + i));
        nf2 = __ldcs(reinterpret_cast<const float4*>(fb + 2 * NVOX + i));
    }

    while (valid) {
        const int i = g * 4;
        const float4 f0 = nf0, f1 = nf1, f2 = nf2;

        // prefetch next iteration's flow
        const int gn = g + GSTRIDE;
        const bool nvalid = (gn < GROUPS);
        if (nvalid) {
            const int i2 = gn * 4;
            nf0 = __ldcs(reinterpret_cast<const float4*>(fb + i2));
            nf1 = __ldcs(reinterpret_cast<const float4*>(fb + NVOX + i2));
            nf2 = __ldcs(reinterpret_cast<const float4*>(fb + 2 * NVOX + i2));
        }

        const int z = i / HW;
        const int rem = i - z * HW;
        const int y = rem / WW;
        const int x = rem - y * WW;

        const float f0a[4] = {f0.x, f0.y, f0.z, f0.w};
        const float f1a[4] = {f1.x, f1.y, f1.z, f1.w};
        const float f2a[4] = {f2.x, f2.y, f2.z, f2.w};

        float oa[4];
        #pragma unroll
        for (int k = 0; k < 4; ++k) {
            // raw px; *0.5f*223.0f == *111.5f bitwise (0.5*223 exact)
            const float pxr = ((float)(x + k) + f0a[k] + 1.0f) * 111.5f;

            float py = (float)y + f1a[k];
            float pz = (float)z + f2a[k];
            py = fminf(fmaxf(py, 0.0f), (float)(HH - 1));
            pz = fminf(fmaxf(pz, 0.0f), (float)(DD - 1));

            const float y0f = floorf(py);
            const float z0f = floorf(pz);
            const float fy = py - y0f;
            const float fz = pz - z0f;
            const int y0 = (int)y0f;
            const int z0 = (int)z0f;
            const int y1 = min(y0 + 1, HH - 1);
            const int z1 = min(z0 + 1, DD - 1);

            float res;
            if (pxr >= (float)(WW - 1)) {
                // border fast path: fx == 0; 4 LDS from the resident slice
                const int r0 = z0 * SP;
                const int r1 = z1 * SP;
                const float v00 = s_slice[r0 + y0];
                const float v01 = s_slice[r0 + y1];
                const float v10 = s_slice[r1 + y0];
                const float v11 = s_slice[r1 + y1];
                const float c0 = v00 + (v01 - v00) * fy;
                const float c1 = v10 + (v11 - v10) * fy;
                res = c0 + (c1 - c0) * fz;
            } else {
                const float px = fmaxf(pxr, 0.0f);      // px < 223 here
                const float x0f = floorf(px);
                const float fx = px - x0f;
                const int x0 = (int)x0f;
                const int x1 = min(x0 + 1, WW - 1);

                const long long zb0 = (long long)z0 * HW;
                const long long zb1 = (long long)z1 * HW;
                const int yb0 = y0 * WW;
                const int yb1 = y1 * WW;

                const float c000 = __ldg(im + zb0 + yb0 + x0);
                const float c001 = __ldg(im + zb0 + yb0 + x1);
                const float c010 = __ldg(im + zb0 + yb1 + x0);
                const float c011 = __ldg(im + zb0 + yb1 + x1);
                const float c100 = __ldg(im + zb1 + yb0 + x0);
                const float c101 = __ldg(im + zb1 + yb0 + x1);
                const float c110 = __ldg(im + zb1 + yb1 + x0);
                const float c111 = __ldg(im + zb1 + yb1 + x1);

                const float c00 = c000 + (c001 - c000) * fx;
                const float c01 = c010 + (c011 - c010) * fx;
                const float c10 = c100 + (c101 - c100) * fx;
                const float c11 = c110 + (c111 - c110) * fx;
                const float c0 = c00 + (c01 - c00) * fy;
                const float c1 = c10 + (c11 - c10) * fy;
                res = c0 + (c1 - c0) * fz;
            }
            oa[k] = res;
        }

        __stcs(reinterpret_cast<float4*>(ob + i),
               make_float4(oa[0], oa[1], oa[2], oa[3]));

        g = gn;
        valid = nvalid;
    }
}

extern "C" void kernel_launch(void* const* d_in, const int* in_sizes, int n_in,
                              void* d_out, int out_size)
{
    const float* img  = (const float*)d_in[0];
    const float* flow = (const float*)d_in[1];
    float* out = (float*)d_out;

    // opt-in to >48KB dynamic smem (idempotent; no allocation involved)
    cudaFuncSetAttribute(st3d_kernel,
                         cudaFuncAttributeMaxDynamicSharedMemorySize, SLICE_BYTES);

    extract_border_kernel<<<(NSLICE + 255) / 256, 256>>>(img);
    st3d_kernel<<<GRID_MAIN, TPB, SLICE_BYTES>>>(img, flow, out);
}